// round 4
// baseline (speedup 1.0000x reference)
#include <cuda_runtime.h>
#include <cuda_bf16.h>
#include <cstdint>

#define N_B    16
#define C_DIM  512
#define HW_DIM 3136
#define D_DIM  512

// tcgen05 available only in the arch-specific (sm_103a/sm_100a) compile pass.
#if defined(__CUDA_ARCH_FEAT_SM103_ALL) || defined(__CUDA_ARCH_FEAT_SM100_ALL) || \
    (defined(__CUDA_ARCH_SPECIFIC__) && (__CUDA_ARCH_SPECIFIC__ == 1030 || __CUDA_ARCH_SPECIFIC__ == 1000))
#define HAS_TCGEN05 1
#else
#define HAS_TCGEN05 0
#endif

// Scratch (allocation-free contract: __device__ globals)
__device__ float g_Q[(size_t)N_B * HW_DIM * D_DIM];   // [n][s][d]
__device__ float g_K[(size_t)N_B * HW_DIM * D_DIM];   // [n][s][d]
__device__ float g_V[(size_t)N_B * HW_DIM * D_DIM];   // [n][s][d]
__device__ float g_S[(size_t)N_B * D_DIM * D_DIM];    // [n][d][e]

// ===================== PTX helpers =====================
__device__ __forceinline__ uint32_t elect_one_pred() {
    uint32_t pred;
    asm volatile("{\n\t.reg .pred p;\n\telect.sync _|p, 0xFFFFFFFF;\n\t"
                 "selp.b32 %0, 1, 0, p;\n\t}" : "=r"(pred));
    return pred;
}
__device__ __forceinline__ uint32_t smem_to_u32(const void* smem_ptr) {
    uint32_t addr;
    asm("{ .reg .u64 tmp; cvta.to.shared.u64 tmp, %1; cvt.u32.u64 %0, tmp; }"
        : "=r"(addr) : "l"(smem_ptr));
    return addr;
}
#define FENCE_PROXY_ASYNC_SHARED_CTA() \
    asm volatile("fence.proxy.async.shared::cta;" ::: "memory")
#define MBARRIER_INIT(mbar_smem_addr, count) \
    asm volatile("mbarrier.init.shared.b64 [%0], %1;" \
        :: "r"((uint32_t)(mbar_smem_addr)), "r"((uint32_t)(count)) : "memory")
__device__ __forceinline__ void mbarrier_inval(uint32_t mbar_smem_addr) {
    asm volatile("mbarrier.inval.shared.b64 [%0];" :: "r"(mbar_smem_addr) : "memory");
}
#define MBARRIER_WAIT_PARITY(mbar_smem_addr, phase_parity) do { \
    uint32_t _mbar = (uint32_t)(mbar_smem_addr); \
    uint32_t _parity = (uint32_t)(phase_parity); \
    uint32_t _done; \
    asm volatile("{\n\t.reg .pred p;\n\t" \
        "mbarrier.try_wait.parity.acquire.cta.shared::cta.b64 p, [%1], %2;\n\t" \
        "selp.b32 %0, 1, 0, p;\n\t}" \
        : "=r"(_done) : "r"(_mbar), "r"(_parity) : "memory"); \
    if (!_done) { \
        asm volatile("{\n\t.reg .pred P1;\n\t" \
            "WAIT_LOOP_%=:\n\t" \
            "mbarrier.try_wait.parity.acquire.cta.shared::cta.b64 P1, [%0], %1, 0x989680;\n\t" \
            "@P1 bra.uni WAIT_DONE_%=;\n\t" \
            "bra.uni WAIT_LOOP_%=;\n\t" \
            "WAIT_DONE_%=:\n\t}" \
            :: "r"(_mbar), "r"(_parity) : "memory"); \
    } \
} while(0)
#define SMEM_SWIZZLE_128B(byte_offset) \
    ((byte_offset) ^ (((byte_offset) >> 3) & 0x70))

#if HAS_TCGEN05
#define TCGEN05_ALLOC(smem_result_addr, nCols) \
    asm volatile("tcgen05.alloc.cta_group::1.sync.aligned.shared::cta.b32 [%0], %1;" \
        :: "r"((uint32_t)(smem_result_addr)), "r"((uint32_t)(nCols)) : "memory")
#define TCGEN05_DEALLOC(tmem_addr, nCols) \
    asm volatile("tcgen05.dealloc.cta_group::1.sync.aligned.b32 %0, %1;" \
        :: "r"(tmem_addr), "r"((uint32_t)(nCols)))
#define TCGEN05_RELINQUISH_ALLOC_PERMIT() \
    asm volatile("tcgen05.relinquish_alloc_permit.cta_group::1.sync.aligned;")
#define TCGEN05_COMMIT(mbar_smem_addr) \
    asm volatile("tcgen05.commit.cta_group::1.mbarrier::arrive::one.shared::cluster.b64 [%0];" \
        :: "r"((uint32_t)(mbar_smem_addr)) : "memory")
#define TCGEN05_FENCE_BEFORE() asm volatile("tcgen05.fence::before_thread_sync;" ::: "memory")
#define TCGEN05_FENCE_AFTER()  asm volatile("tcgen05.fence::after_thread_sync;" ::: "memory")
#define TCGEN05_WAIT_LD()      asm volatile("tcgen05.wait::ld.sync.aligned;" ::: "memory")
#define TCGEN05_LD_32X32B_X32(r, tmem_addr) \
    asm volatile("tcgen05.ld.sync.aligned.32x32b.x32.b32 " \
        "{%0, %1, %2, %3, %4, %5, %6, %7, %8, %9, %10, %11, %12, %13, %14, %15, " \
        " %16, %17, %18, %19, %20, %21, %22, %23, %24, %25, %26, %27, %28, %29, %30, %31}, [%32];" \
        : "=r"((r)[0]),  "=r"((r)[1]),  "=r"((r)[2]),  "=r"((r)[3]), \
          "=r"((r)[4]),  "=r"((r)[5]),  "=r"((r)[6]),  "=r"((r)[7]), \
          "=r"((r)[8]),  "=r"((r)[9]),  "=r"((r)[10]), "=r"((r)[11]), \
          "=r"((r)[12]), "=r"((r)[13]), "=r"((r)[14]), "=r"((r)[15]), \
          "=r"((r)[16]), "=r"((r)[17]), "=r"((r)[18]), "=r"((r)[19]), \
          "=r"((r)[20]), "=r"((r)[21]), "=r"((r)[22]), "=r"((r)[23]), \
          "=r"((r)[24]), "=r"((r)[25]), "=r"((r)[26]), "=r"((r)[27]), \
          "=r"((r)[28]), "=r"((r)[29]), "=r"((r)[30]), "=r"((r)[31]) \
        : "r"(tmem_addr))

static constexpr uint64_t SMEM_DESC_BASE_SW128 =
    (uint64_t(2)  << 61) | (uint64_t(1) << 46) | (uint64_t(64) << 32) | (uint64_t(1) << 16);
#define MAKE_SMEM_DESC(base_addr) \
    (SMEM_DESC_BASE_SW128 | ((uint64_t)((base_addr) >> 4) & 0x3FFF))

// SS-mode cg1 kind::f16 MMA (bf16 in, fp32 accum)
__device__ __forceinline__ void mma_f16_ss(uint32_t d_tmem, uint64_t a_desc,
                                           uint64_t b_desc, uint32_t idesc, bool acc)
{
    uint32_t en = acc ? 1u : 0u;
    asm volatile(
        "{\n\t.reg .pred p;\n\tsetp.ne.u32 p, %4, 0;\n\t"
        "tcgen05.mma.cta_group::1.kind::f16 [%0], %1, %2, %3, {%5, %5, %5, %5}, p;\n\t}"
        :: "r"(d_tmem), "l"(a_desc), "l"(b_desc), "r"(idesc), "r"(en), "r"(0u)
        : "memory");
}
#endif // HAS_TCGEN05

// idesc: F32 accum (1<<4), A=BF16 (1<<7), B=BF16 (1<<10), N=128, M=128
static constexpr uint32_t IDESC_BF16_128x128 =
    (1u << 4) | (1u << 7) | (1u << 10) | ((128u / 8u) << 17) | ((128u / 16u) << 24);

// ===================== smem layout (dynamic) =====================
static constexpr int OFF_TMEM = 0;
static constexpr int OFF_MBAR = 8;
static constexpr int OFF_BIAS = 16;
static constexpr int OFF_AHI  = 1024;
static constexpr int OFF_ALO  = 17408;
static constexpr int OFF_BHI  = 33792;
static constexpr int OFF_BLO  = 50176;
static constexpr int SMEM_BYTES = 66560;

__device__ __forceinline__ uint32_t bf2u(__nv_bfloat162 h) {
    uint32_t u; memcpy(&u, &h, 4); return u;
}

// K-major source: P[k*ld + m]. Each thread: one k row (tid>>2), 32 m values.
__device__ __forceinline__ void load_kmaj(const float* __restrict__ P, int kt,
                                          int base0, int rows, int ld, int tid,
                                          char* hi, char* lo)
{
    const int k  = tid >> 2;
    const int ms = (tid & 3) * 32;
    const float* rowp = P + (long long)(kt + k) * ld;
    #pragma unroll
    for (int j = 0; j < 8; j++) {
        int m = base0 + ms + j * 4;
        if (m > rows - 4) m = rows - 4;          // rows % 4 == 0 always
        float4 v = *(const float4*)(rowp + m);
        const int r = ms + j * 4;
        float f[4] = {v.x, v.y, v.z, v.w};
        #pragma unroll
        for (int e = 0; e < 4; e++) {
            __nv_bfloat16 h = __float2bfloat16(f[e]);
            __nv_bfloat16 l = __float2bfloat16(f[e] - __bfloat162float(h));
            uint32_t off = SMEM_SWIZZLE_128B((uint32_t)((r + e) * 128 + k * 2));
            *(__nv_bfloat16*)(hi + off) = h;
            *(__nv_bfloat16*)(lo + off) = l;
        }
    }
}

// M-major source: P[m*ld + k]. Each thread: one row (tid>>1), 32 k values.
__device__ __forceinline__ void load_mmaj(const float* __restrict__ P, int kt,
                                          int base0, int rows, int ld, int tid,
                                          char* hi, char* lo)
{
    const int r    = tid >> 1;
    const int kseg = (tid & 1) * 32;
    int row = base0 + r;
    if (row > rows - 1) row = rows - 1;
    const float* p = P + (long long)row * ld + kt + kseg;
    #pragma unroll
    for (int g = 0; g < 4; g++) {
        float4 v0 = *(const float4*)(p + g * 8);
        float4 v1 = *(const float4*)(p + g * 8 + 4);
        __nv_bfloat162 h0 = __floats2bfloat162_rn(v0.x, v0.y);
        __nv_bfloat162 h1 = __floats2bfloat162_rn(v0.z, v0.w);
        __nv_bfloat162 h2 = __floats2bfloat162_rn(v1.x, v1.y);
        __nv_bfloat162 h3 = __floats2bfloat162_rn(v1.z, v1.w);
        float2 f0 = __bfloat1622float2(h0), f1 = __bfloat1622float2(h1);
        float2 f2 = __bfloat1622float2(h2), f3 = __bfloat1622float2(h3);
        __nv_bfloat162 l0 = __floats2bfloat162_rn(v0.x - f0.x, v0.y - f0.y);
        __nv_bfloat162 l1 = __floats2bfloat162_rn(v0.z - f1.x, v0.w - f1.y);
        __nv_bfloat162 l2 = __floats2bfloat162_rn(v1.x - f2.x, v1.y - f2.y);
        __nv_bfloat162 l3 = __floats2bfloat162_rn(v1.z - f3.x, v1.w - f3.y);
        uint4 hv = {bf2u(h0), bf2u(h1), bf2u(h2), bf2u(h3)};
        uint4 lv = {bf2u(l0), bf2u(l1), bf2u(l2), bf2u(l3)};
        uint32_t off = SMEM_SWIZZLE_128B((uint32_t)(r * 128 + (kseg + g * 8) * 2));
        *(uint4*)(hi + off) = hv;
        *(uint4*)(lo + off) = lv;
    }
}

// ===== SIMT fallback pieces (compute_103 pass only executes these) =====
constexpr int FB_BK = 16;
constexpr int FB_SROW = 132;

template <bool KMAJ>
__device__ __forceinline__ void fb_load(const float* __restrict__ P, int kt,
                                        int base0, int rows, int ld, int tid,
                                        float4 r[2])
{
    if (KMAJ) {
        const int k = tid >> 4;
        int m = base0 + (tid & 15) * 8;
        m = min(m, rows - 8);
        const float* p = P + (long long)(kt + k) * ld + m;
        r[0] = *(const float4*)p;
        r[1] = *(const float4*)(p + 4);
    } else {
        int m = base0 + (tid >> 1);
        m = min(m, rows - 1);
        const int kk = (tid & 1) * 8;
        const float* p = P + (long long)m * ld + kt + kk;
        r[0] = *(const float4*)p;
        r[1] = *(const float4*)(p + 4);
    }
}
template <bool KMAJ>
__device__ __forceinline__ void fb_store(float (*Sm)[FB_SROW], int tid,
                                         const float4 r[2])
{
    if (KMAJ) {
        const int k = tid >> 4;
        const int m = (tid & 15) * 8;
        *(float4*)&Sm[k][m]     = r[0];
        *(float4*)&Sm[k][m + 4] = r[1];
    } else {
        const int m  = tid >> 1;
        const int kk = (tid & 1) * 8;
        Sm[kk + 0][m] = r[0].x; Sm[kk + 1][m] = r[0].y;
        Sm[kk + 2][m] = r[0].z; Sm[kk + 3][m] = r[0].w;
        Sm[kk + 4][m] = r[1].x; Sm[kk + 5][m] = r[1].y;
        Sm[kk + 6][m] = r[1].z; Sm[kk + 7][m] = r[1].w;
    }
}

// GEMM: C[m][n] = sum_k a(k,m)*b(k,n) (+bias[n]); 128x128 tile per CTA.
template <bool A_KMAJOR, bool B_KMAJOR, bool ADD_BIAS>
__global__ __launch_bounds__(256, 2)
void tc_gemm(const float* __restrict__ A, const float* __restrict__ B,
             const float* __restrict__ bias, float* __restrict__ C,
             int M, int Nn, int K, int lda, int ldb, int ldc,
             long long strideA, long long strideB, long long strideC)
{
    extern __shared__ char smem[];
    const int tid = threadIdx.x;
    const int n0 = blockIdx.x * 128;
    const int m0 = blockIdx.y * 128;

    A += strideA * blockIdx.z;
    B += strideB * blockIdx.z;
    C += strideC * blockIdx.z;

#if HAS_TCGEN05
    const uint32_t sb = smem_to_u32(smem);
    const int wid = tid >> 5;

    if (tid == 0) MBARRIER_INIT(sb + OFF_MBAR, 1);
    if (wid == 0) {
        TCGEN05_ALLOC(sb + OFF_TMEM, 128);
        TCGEN05_RELINQUISH_ALLOC_PERMIT();
    }
    if (ADD_BIAS && tid < 128)
        *(float*)(smem + OFF_BIAS + tid * 4) = bias[n0 + tid];
    __syncthreads();

    uint32_t tmem;
    asm volatile("ld.shared.b32 %0, [%1];" : "=r"(tmem) : "r"(sb + OFF_TMEM));

    int phase = 0;
    for (int kt = 0; kt < K; kt += 64) {
        if (A_KMAJOR) load_kmaj(A, kt, m0, M, lda, tid, smem + OFF_AHI, smem + OFF_ALO);
        else          load_mmaj(A, kt, m0, M, lda, tid, smem + OFF_AHI, smem + OFF_ALO);
        if (B_KMAJOR) load_kmaj(B, kt, n0, Nn, ldb, tid, smem + OFF_BHI, smem + OFF_BLO);
        else          load_mmaj(B, kt, n0, Nn, ldb, tid, smem + OFF_BHI, smem + OFF_BLO);

        FENCE_PROXY_ASYNC_SHARED_CTA();
        __syncthreads();

        if (wid == 0 && elect_one_pred()) {
            const uint64_t dAh = MAKE_SMEM_DESC(sb + OFF_AHI);
            const uint64_t dAl = MAKE_SMEM_DESC(sb + OFF_ALO);
            const uint64_t dBh = MAKE_SMEM_DESC(sb + OFF_BHI);
            const uint64_t dBl = MAKE_SMEM_DESC(sb + OFF_BLO);
            #pragma unroll
            for (int ks = 0; ks < 4; ks++) {
                const uint64_t o = (uint64_t)(ks * 2);
                mma_f16_ss(tmem, dAh + o, dBh + o, IDESC_BF16_128x128,
                           !(kt == 0 && ks == 0));
                mma_f16_ss(tmem, dAh + o, dBl + o, IDESC_BF16_128x128, true);
                mma_f16_ss(tmem, dAl + o, dBh + o, IDESC_BF16_128x128, true);
            }
            TCGEN05_COMMIT(sb + OFF_MBAR);
        }
        MBARRIER_WAIT_PARITY(sb + OFF_MBAR, phase);
        phase ^= 1;
    }
    TCGEN05_FENCE_AFTER();

    // ---- epilogue: lanes 0..127 = M rows; TMEM cols = N ----
    if (tid < 128) {
        const int m = m0 + tid;
        const bool mok = (m < M);
        float* crow = C + (long long)m * ldc;
        const float* bs = (const float*)(smem + OFF_BIAS);
        #pragma unroll
        for (int b = 0; b < 4; b++) {
            uint32_t r[32];
            TCGEN05_LD_32X32B_X32(r, tmem + b * 32);
            TCGEN05_WAIT_LD();
            if (mok) {
                #pragma unroll
                for (int j = 0; j < 8; j++) {
                    const int nc = b * 32 + j * 4;
                    const int n = n0 + nc;
                    if (n + 4 <= Nn) {
                        float4 o;
                        o.x = __uint_as_float(r[j * 4 + 0]);
                        o.y = __uint_as_float(r[j * 4 + 1]);
                        o.z = __uint_as_float(r[j * 4 + 2]);
                        o.w = __uint_as_float(r[j * 4 + 3]);
                        if (ADD_BIAS) {
                            o.x += bs[nc + 0]; o.y += bs[nc + 1];
                            o.z += bs[nc + 2]; o.w += bs[nc + 3];
                        }
                        *(float4*)(crow + n) = o;
                    }
                }
            }
        }
    }
    TCGEN05_FENCE_BEFORE();
    __syncthreads();
    if (tid == 0) mbarrier_inval(sb + OFF_MBAR);
    if (wid == 0) TCGEN05_DEALLOC(tmem, 128);

#else  // ===== SIMT fallback (plain sm_103 target) =====
    float (*As)[FB_SROW] = (float(*)[FB_SROW])(smem);
    float (*Bs)[FB_SROW] = (float(*)[FB_SROW])(smem + FB_BK * FB_SROW * 4);

    const int tx = tid & 15;
    const int ty = tid >> 4;

    float acc[8][8] = {};
    float4 ra[2], rb[2];

    fb_load<A_KMAJOR>(A, 0, m0, M,  lda, tid, ra);
    fb_load<B_KMAJOR>(B, 0, n0, Nn, ldb, tid, rb);

    for (int kt = 0; kt < K; kt += FB_BK) {
        fb_store<A_KMAJOR>(As, tid, ra);
        fb_store<B_KMAJOR>(Bs, tid, rb);
        __syncthreads();

        if (kt + FB_BK < K) {
            fb_load<A_KMAJOR>(A, kt + FB_BK, m0, M,  lda, tid, ra);
            fb_load<B_KMAJOR>(B, kt + FB_BK, n0, Nn, ldb, tid, rb);
        }

        #pragma unroll
        for (int k = 0; k < FB_BK; k++) {
            float4 a0 = *(const float4*)&As[k][ty * 8];
            float4 a1 = *(const float4*)&As[k][ty * 8 + 4];
            float4 b0 = *(const float4*)&Bs[k][tx * 8];
            float4 b1 = *(const float4*)&Bs[k][tx * 8 + 4];
            float a[8] = {a0.x, a0.y, a0.z, a0.w, a1.x, a1.y, a1.z, a1.w};
            float b[8] = {b0.x, b0.y, b0.z, b0.w, b1.x, b1.y, b1.z, b1.w};
            #pragma unroll
            for (int i = 0; i < 8; i++)
                #pragma unroll
                for (int j = 0; j < 8; j++)
                    acc[i][j] += a[i] * b[j];
        }
        __syncthreads();
    }

    float bn[8] = {};
    const int nbase = n0 + tx * 8;
    const bool n_ok = (nbase < Nn);
    if (ADD_BIAS && n_ok) {
        float4 b0 = *(const float4*)(bias + nbase);
        float4 b1 = *(const float4*)(bias + nbase + 4);
        bn[0]=b0.x; bn[1]=b0.y; bn[2]=b0.z; bn[3]=b0.w;
        bn[4]=b1.x; bn[5]=b1.y; bn[6]=b1.z; bn[7]=b1.w;
    }
    if (n_ok) {
        #pragma unroll
        for (int i = 0; i < 8; i++) {
            const int m = m0 + ty * 8 + i;
            if (m < M) {
                float4 o0, o1;
                o0.x = acc[i][0] + bn[0]; o0.y = acc[i][1] + bn[1];
                o0.z = acc[i][2] + bn[2]; o0.w = acc[i][3] + bn[3];
                o1.x = acc[i][4] + bn[4]; o1.y = acc[i][5] + bn[5];
                o1.z = acc[i][6] + bn[6]; o1.w = acc[i][7] + bn[7];
                float* cp = C + (long long)m * ldc + nbase;
                *(float4*)cp       = o0;
                *(float4*)(cp + 4) = o1;
            }
        }
    }
#endif
}

// Softmax over rows of length D_DIM (=512). One block (256 threads) per row.
__global__ __launch_bounds__(256)
void softmax_kernel(float* __restrict__ S)
{
    const long long row = blockIdx.x;
    float* p = S + row * D_DIM;
    const int t = threadIdx.x;

    const float a = p[t];
    const float b = p[t + 256];

    __shared__ float red_max[8];
    __shared__ float red_sum[8];

    float m = fmaxf(a, b);
    #pragma unroll
    for (int o = 16; o > 0; o >>= 1)
        m = fmaxf(m, __shfl_xor_sync(0xffffffffu, m, o));
    if ((t & 31) == 0) red_max[t >> 5] = m;
    __syncthreads();
    float rowmax = red_max[0];
    #pragma unroll
    for (int i = 1; i < 8; i++) rowmax = fmaxf(rowmax, red_max[i]);

    const float ea = __expf(a - rowmax);
    const float eb = __expf(b - rowmax);
    float s = ea + eb;
    #pragma unroll
    for (int o = 16; o > 0; o >>= 1)
        s += __shfl_xor_sync(0xffffffffu, s, o);
    if ((t & 31) == 0) red_sum[t >> 5] = s;
    __syncthreads();
    float tot = 0.f;
    #pragma unroll
    for (int i = 0; i < 8; i++) tot += red_sum[i];
    const float inv = 1.0f / tot;

    p[t]       = ea * inv;
    p[t + 256] = eb * inv;
}

extern "C" void kernel_launch(void* const* d_in, const int* in_sizes, int n_in,
                              void* d_out, int out_size)
{
    (void)in_sizes; (void)n_in; (void)out_size;
    const float* bf = (const float*)d_in[0];  // [N, C, HW]
    const float* Wq = (const float*)d_in[1];  // [D, C]
    const float* bq = (const float*)d_in[2];  // [D]
    const float* Wk = (const float*)d_in[3];
    const float* bk = (const float*)d_in[4];
    const float* Wv = (const float*)d_in[5];
    const float* bv = (const float*)d_in[6];
    float* out = (float*)d_out;               // [N, D, HW]

    float *Qp, *Kp, *Vp, *Sp;
    cudaGetSymbolAddress((void**)&Qp, g_Q);
    cudaGetSymbolAddress((void**)&Kp, g_K);
    cudaGetSymbolAddress((void**)&Vp, g_V);
    cudaGetSymbolAddress((void**)&Sp, g_S);

    cudaFuncSetAttribute(tc_gemm<true, false, true>,
        cudaFuncAttributeMaxDynamicSharedMemorySize, SMEM_BYTES);
    cudaFuncSetAttribute(tc_gemm<true, true, false>,
        cudaFuncAttributeMaxDynamicSharedMemorySize, SMEM_BYTES);
    cudaFuncSetAttribute(tc_gemm<false, false, false>,
        cudaFuncAttributeMaxDynamicSharedMemorySize, SMEM_BYTES);

    const dim3 blk(256);
    const long long sA_x = (long long)C_DIM * HW_DIM;
    const long long sQ   = (long long)HW_DIM * D_DIM;
    const long long sS   = (long long)D_DIM * D_DIM;

    // 1) Q/K/V: Out[n][s][d] = sum_c x(k=c,m=s)*W(n=d,k=c) + b[d]
    const dim3 g_qkv(D_DIM / 128, (HW_DIM + 127) / 128, N_B);   // (4, 25, 16)
    tc_gemm<true, false, true><<<g_qkv, blk, SMEM_BYTES>>>(
        bf, Wq, bq, Qp, HW_DIM, D_DIM, C_DIM, HW_DIM, C_DIM, D_DIM, sA_x, 0, sQ);
    tc_gemm<true, false, true><<<g_qkv, blk, SMEM_BYTES>>>(
        bf, Wk, bk, Kp, HW_DIM, D_DIM, C_DIM, HW_DIM, C_DIM, D_DIM, sA_x, 0, sQ);
    tc_gemm<true, false, true><<<g_qkv, blk, SMEM_BYTES>>>(
        bf, Wv, bv, Vp, HW_DIM, D_DIM, C_DIM, HW_DIM, C_DIM, D_DIM, sA_x, 0, sQ);

    // 2) scores: S[n][d][e] = sum_s Q[s][d]*K[s][e]  (both k-major, K=HW)
    const dim3 g_sc(D_DIM / 128, D_DIM / 128, N_B);             // (4, 4, 16)
    tc_gemm<true, true, false><<<g_sc, blk, SMEM_BYTES>>>(
        Qp, Kp, nullptr, Sp, D_DIM, D_DIM, HW_DIM, D_DIM, D_DIM, D_DIM, sQ, sQ, sS);

    // 3) softmax over last dim of S
    softmax_kernel<<<N_B * D_DIM, 256>>>(Sp);

    // 4) out: O[n][d][s] = sum_e S[d][e]*V[s][e]  (both m-major)
    const dim3 g_out((HW_DIM + 127) / 128, D_DIM / 128, N_B);   // (25, 4, 16)
    tc_gemm<false, false, false><<<g_out, blk, SMEM_BYTES>>>(
        Sp, Vp, nullptr, out, D_DIM, HW_DIM, D_DIM, D_DIM, D_DIM, HW_DIM,
        sS, sQ, (long long)D_DIM * HW_DIM);
}

// round 6
// speedup vs baseline: 3.5739x; 3.5739x over previous
#include <cuda_runtime.h>
#include <cuda_bf16.h>
#include <cstdint>

#define N_B    16
#define C_DIM  512
#define HW_DIM 3136
#define D_DIM  512

// tcgen05 available only in the arch-specific (sm_103a/sm_100a) compile pass.
#if defined(__CUDA_ARCH_FEAT_SM103_ALL) || defined(__CUDA_ARCH_FEAT_SM100_ALL) || \
    (defined(__CUDA_ARCH_SPECIFIC__) && (__CUDA_ARCH_SPECIFIC__ == 1030 || __CUDA_ARCH_SPECIFIC__ == 1000))
#define HAS_TCGEN05 1
#else
#define HAS_TCGEN05 0
#endif

// ===================== scratch (__device__ globals; no allocs) =====================
__device__ __nv_bfloat16 g_xt_hi[(size_t)N_B * HW_DIM * C_DIM];  // [n][s][c]
__device__ __nv_bfloat16 g_xt_lo[(size_t)N_B * HW_DIM * C_DIM];
__device__ __nv_bfloat16 g_w_hi[3][(size_t)D_DIM * C_DIM];       // [qkv][d][c]
__device__ __nv_bfloat16 g_w_lo[3][(size_t)D_DIM * C_DIM];
__device__ __nv_bfloat16 g_q_hi[(size_t)N_B * D_DIM * HW_DIM];   // [n][d][s]
__device__ __nv_bfloat16 g_q_lo[(size_t)N_B * D_DIM * HW_DIM];
__device__ __nv_bfloat16 g_k_hi[(size_t)N_B * D_DIM * HW_DIM];   // [n][e][s]
__device__ __nv_bfloat16 g_k_lo[(size_t)N_B * D_DIM * HW_DIM];
__device__ __nv_bfloat16 g_v_hi[(size_t)N_B * HW_DIM * D_DIM];   // [n][s][d]
__device__ __nv_bfloat16 g_v_lo[(size_t)N_B * HW_DIM * D_DIM];
__device__ float         g_S[(size_t)N_B * D_DIM * D_DIM];       // [n][d][e]
__device__ __nv_bfloat16 g_att_hi[(size_t)N_B * D_DIM * D_DIM];  // [n][d][e]
__device__ __nv_bfloat16 g_att_lo[(size_t)N_B * D_DIM * D_DIM];

// ===================== PTX helpers =====================
__device__ __forceinline__ uint32_t elect_one_pred() {
    uint32_t pred;
    asm volatile("{\n\t.reg .pred p;\n\telect.sync _|p, 0xFFFFFFFF;\n\t"
                 "selp.b32 %0, 1, 0, p;\n\t}" : "=r"(pred));
    return pred;
}
__device__ __forceinline__ uint32_t smem_to_u32(const void* smem_ptr) {
    uint32_t addr;
    asm("{ .reg .u64 tmp; cvta.to.shared.u64 tmp, %1; cvt.u32.u64 %0, tmp; }"
        : "=r"(addr) : "l"(smem_ptr));
    return addr;
}
#define FENCE_PROXY_ASYNC_SHARED_CTA() \
    asm volatile("fence.proxy.async.shared::cta;" ::: "memory")
#define MBARRIER_INIT(mbar_smem_addr, count) \
    asm volatile("mbarrier.init.shared.b64 [%0], %1;" \
        :: "r"((uint32_t)(mbar_smem_addr)), "r"((uint32_t)(count)) : "memory")
__device__ __forceinline__ void mbarrier_inval(uint32_t mbar_smem_addr) {
    asm volatile("mbarrier.inval.shared.b64 [%0];" :: "r"(mbar_smem_addr) : "memory");
}
#define MBARRIER_WAIT_PARITY(mbar_smem_addr, phase_parity) do { \
    uint32_t _mbar = (uint32_t)(mbar_smem_addr); \
    uint32_t _parity = (uint32_t)(phase_parity); \
    uint32_t _done; \
    asm volatile("{\n\t.reg .pred p;\n\t" \
        "mbarrier.try_wait.parity.acquire.cta.shared::cta.b64 p, [%1], %2;\n\t" \
        "selp.b32 %0, 1, 0, p;\n\t}" \
        : "=r"(_done) : "r"(_mbar), "r"(_parity) : "memory"); \
    if (!_done) { \
        asm volatile("{\n\t.reg .pred P1;\n\t" \
            "WAIT_LOOP_%=:\n\t" \
            "mbarrier.try_wait.parity.acquire.cta.shared::cta.b64 P1, [%0], %1, 0x989680;\n\t" \
            "@P1 bra.uni WAIT_DONE_%=;\n\t" \
            "bra.uni WAIT_LOOP_%=;\n\t" \
            "WAIT_DONE_%=:\n\t}" \
            :: "r"(_mbar), "r"(_parity) : "memory"); \
    } \
} while(0)
#define SMEM_SWIZZLE_128B(byte_offset) \
    ((byte_offset) ^ (((byte_offset) >> 3) & 0x70))

#if HAS_TCGEN05
#define TCGEN05_ALLOC(smem_result_addr, nCols) \
    asm volatile("tcgen05.alloc.cta_group::1.sync.aligned.shared::cta.b32 [%0], %1;" \
        :: "r"((uint32_t)(smem_result_addr)), "r"((uint32_t)(nCols)) : "memory")
#define TCGEN05_DEALLOC(tmem_addr, nCols) \
    asm volatile("tcgen05.dealloc.cta_group::1.sync.aligned.b32 %0, %1;" \
        :: "r"(tmem_addr), "r"((uint32_t)(nCols)))
#define TCGEN05_RELINQUISH_ALLOC_PERMIT() \
    asm volatile("tcgen05.relinquish_alloc_permit.cta_group::1.sync.aligned;")
#define TCGEN05_COMMIT(mbar_smem_addr) \
    asm volatile("tcgen05.commit.cta_group::1.mbarrier::arrive::one.shared::cluster.b64 [%0];" \
        :: "r"((uint32_t)(mbar_smem_addr)) : "memory")
#define TCGEN05_FENCE_BEFORE() asm volatile("tcgen05.fence::before_thread_sync;" ::: "memory")
#define TCGEN05_FENCE_AFTER()  asm volatile("tcgen05.fence::after_thread_sync;" ::: "memory")
#define TCGEN05_WAIT_LD()      asm volatile("tcgen05.wait::ld.sync.aligned;" ::: "memory")
#define TCGEN05_LD_32X32B_X32(r, tmem_addr) \
    asm volatile("tcgen05.ld.sync.aligned.32x32b.x32.b32 " \
        "{%0, %1, %2, %3, %4, %5, %6, %7, %8, %9, %10, %11, %12, %13, %14, %15, " \
        " %16, %17, %18, %19, %20, %21, %22, %23, %24, %25, %26, %27, %28, %29, %30, %31}, [%32];" \
        : "=r"((r)[0]),  "=r"((r)[1]),  "=r"((r)[2]),  "=r"((r)[3]), \
          "=r"((r)[4]),  "=r"((r)[5]),  "=r"((r)[6]),  "=r"((r)[7]), \
          "=r"((r)[8]),  "=r"((r)[9]),  "=r"((r)[10]), "=r"((r)[11]), \
          "=r"((r)[12]), "=r"((r)[13]), "=r"((r)[14]), "=r"((r)[15]), \
          "=r"((r)[16]), "=r"((r)[17]), "=r"((r)[18]), "=r"((r)[19]), \
          "=r"((r)[20]), "=r"((r)[21]), "=r"((r)[22]), "=r"((r)[23]), \
          "=r"((r)[24]), "=r"((r)[25]), "=r"((r)[26]), "=r"((r)[27]), \
          "=r"((r)[28]), "=r"((r)[29]), "=r"((r)[30]), "=r"((r)[31]) \
        : "r"(tmem_addr))

static constexpr uint64_t SMEM_DESC_BASE_SW128 =
    (uint64_t(2)  << 61) | (uint64_t(1) << 46) | (uint64_t(64) << 32) | (uint64_t(1) << 16);
#define MAKE_SMEM_DESC(base_addr) \
    (SMEM_DESC_BASE_SW128 | ((uint64_t)((base_addr) >> 4) & 0x3FFF))

// SS-mode cg1 kind::f16 MMA (bf16 in, fp32 accum)
__device__ __forceinline__ void mma_f16_ss(uint32_t d_tmem, uint64_t a_desc,
                                           uint64_t b_desc, uint32_t idesc, bool acc)
{
    uint32_t en = acc ? 1u : 0u;
    asm volatile(
        "{\n\t.reg .pred p;\n\tsetp.ne.u32 p, %4, 0;\n\t"
        "tcgen05.mma.cta_group::1.kind::f16 [%0], %1, %2, %3, {%5, %5, %5, %5}, p;\n\t}"
        :: "r"(d_tmem), "l"(a_desc), "l"(b_desc), "r"(idesc), "r"(en), "r"(0u)
        : "memory");
}
#endif // HAS_TCGEN05

// idesc: F32 accum (1<<4), A=BF16 (1<<7), B=BF16 (1<<10), N=128, M=128
static constexpr uint32_t IDESC_BF16_128x128 =
    (1u << 4) | (1u << 7) | (1u << 10) | ((128u / 8u) << 17) | ((128u / 16u) << 24);

// ===================== smem layout (dynamic) =====================
static constexpr int OFF_TMEM = 0;
static constexpr int OFF_MBAR = 8;
static constexpr int OFF_BIAS = 16;
static constexpr int OFF_AHI  = 1024;
static constexpr int OFF_ALO  = 17408;
static constexpr int OFF_BHI  = 33792;
static constexpr int OFF_BLO  = 50176;
static constexpr int SMEM_BYTES = 66560;

// Copy a 128-row x 64-col bf16 tile (rows contiguous in gmem, ld elems) into
// SW128-swizzled K-major smem (128 rows x 128B). 16KB = 1024 16B-units =
// 256 threads x 4 x uint4.
__device__ __forceinline__ void copy_tile(const __nv_bfloat16* __restrict__ src,
                                          int row0, int rows, long long ld, int kt,
                                          char* dst, int tid)
{
    #pragma unroll
    for (int i = 0; i < 4; i++) {
        const int idx = i * 256 + tid;       // 0..1023 16B-units
        const int r = idx >> 3;              // 0..127
        const int c = idx & 7;               // 0..7
        int gr = row0 + r;
        gr = min(gr, rows - 1);
        uint4 v = *(const uint4*)(src + (long long)gr * ld + kt + c * 8);
        *(uint4*)(dst + SMEM_SWIZZLE_128B((uint32_t)(r * 128 + c * 16))) = v;
    }
}

__device__ __forceinline__ void split_store(float v, __nv_bfloat16* hi, __nv_bfloat16* lo)
{
    __nv_bfloat16 h = __float2bfloat16(v);
    *hi = h;
    *lo = __float2bfloat16(v - __bfloat162float(h));
}

// =====================================================================
// GEMM on pre-split bf16 planes: C[m][n] = sum_k A[m][k]*B[n][k] (3-term)
// A planes: [M][K] rows contiguous; B planes: [N][K] rows contiguous.
// BIAS_MODE: 0=none, 1=bias[m], 2=bias[n]. OUT_BF16: write hi/lo planes.
// =====================================================================
template <int BIAS_MODE, bool OUT_BF16>
__global__ __launch_bounds__(256, 2)
void tc_gemm_planes(const __nv_bfloat16* __restrict__ Ahi,
                    const __nv_bfloat16* __restrict__ Alo,
                    const __nv_bfloat16* __restrict__ Bhi,
                    const __nv_bfloat16* __restrict__ Blo,
                    const float* __restrict__ bias,
                    float* __restrict__ Cf,
                    __nv_bfloat16* __restrict__ Chi,
                    __nv_bfloat16* __restrict__ Clo,
                    int M, int Nn, int K, int ldc,
                    long long strideA, long long strideB, long long strideC)
{
    extern __shared__ char smem[];
    const int tid = threadIdx.x;
    const int n0 = blockIdx.x * 128;
    const int m0 = blockIdx.y * 128;

    Ahi += strideA * blockIdx.z;  Alo += strideA * blockIdx.z;
    Bhi += strideB * blockIdx.z;  Blo += strideB * blockIdx.z;
    if (Cf)  Cf  += strideC * blockIdx.z;
    if (Chi) { Chi += strideC * blockIdx.z; Clo += strideC * blockIdx.z; }

#if HAS_TCGEN05
    const uint32_t sb = smem_to_u32(smem);
    const int wid = tid >> 5;

    if (tid == 0) MBARRIER_INIT(sb + OFF_MBAR, 1);
    if (wid == 0) {
        TCGEN05_ALLOC(sb + OFF_TMEM, 128);
        TCGEN05_RELINQUISH_ALLOC_PERMIT();
    }
    if (BIAS_MODE == 2 && tid < 128)
        *(float*)(smem + OFF_BIAS + tid * 4) = bias[n0 + tid];
    __syncthreads();

    uint32_t tmem;
    asm volatile("ld.shared.b32 %0, [%1];" : "=r"(tmem) : "r"(sb + OFF_TMEM));

    int phase = 0;
    for (int kt = 0; kt < K; kt += 64) {
        copy_tile(Ahi, m0, M,  K, kt, smem + OFF_AHI, tid);
        copy_tile(Alo, m0, M,  K, kt, smem + OFF_ALO, tid);
        copy_tile(Bhi, n0, Nn, K, kt, smem + OFF_BHI, tid);
        copy_tile(Blo, n0, Nn, K, kt, smem + OFF_BLO, tid);

        FENCE_PROXY_ASYNC_SHARED_CTA();
        __syncthreads();

        if (wid == 0 && elect_one_pred()) {
            const uint64_t dAh = MAKE_SMEM_DESC(sb + OFF_AHI);
            const uint64_t dAl = MAKE_SMEM_DESC(sb + OFF_ALO);
            const uint64_t dBh = MAKE_SMEM_DESC(sb + OFF_BHI);
            const uint64_t dBl = MAKE_SMEM_DESC(sb + OFF_BLO);
            #pragma unroll
            for (int ks = 0; ks < 4; ks++) {
                const uint64_t o = (uint64_t)(ks * 2);
                mma_f16_ss(tmem, dAh + o, dBh + o, IDESC_BF16_128x128,
                           !(kt == 0 && ks == 0));
                mma_f16_ss(tmem, dAh + o, dBl + o, IDESC_BF16_128x128, true);
                mma_f16_ss(tmem, dAl + o, dBh + o, IDESC_BF16_128x128, true);
            }
            TCGEN05_COMMIT(sb + OFF_MBAR);
        }
        MBARRIER_WAIT_PARITY(sb + OFF_MBAR, phase);
        phase ^= 1;
    }
    TCGEN05_FENCE_AFTER();

    // ---- epilogue: lanes 0..127 = M rows; TMEM cols = N ----
    if (tid < 128) {
        const int m = m0 + tid;
        const bool mok = (m < M);
        const float bm = (BIAS_MODE == 1 && mok) ? bias[m] : 0.0f;
        const float* bs = (const float*)(smem + OFF_BIAS);
        #pragma unroll
        for (int b = 0; b < 4; b++) {
            uint32_t r[32];
            TCGEN05_LD_32X32B_X32(r, tmem + b * 32);
            TCGEN05_WAIT_LD();
            if (mok) {
                #pragma unroll
                for (int j = 0; j < 8; j++) {
                    const int nc = b * 32 + j * 4;
                    const int n = n0 + nc;
                    if (n + 4 <= Nn) {
                        float v[4];
                        #pragma unroll
                        for (int e = 0; e < 4; e++) {
                            v[e] = __uint_as_float(r[j * 4 + e]);
                            if (BIAS_MODE == 1) v[e] += bm;
                            if (BIAS_MODE == 2) v[e] += bs[nc + e];
                        }
                        if (OUT_BF16) {
                            __nv_bfloat16 h[4], l[4];
                            #pragma unroll
                            for (int e = 0; e < 4; e++) {
                                h[e] = __float2bfloat16(v[e]);
                                l[e] = __float2bfloat16(v[e] - __bfloat162float(h[e]));
                            }
                            uint2 hp, lp;
                            memcpy(&hp.x, &h[0], 4); memcpy(&hp.y, &h[2], 4);
                            memcpy(&lp.x, &l[0], 4); memcpy(&lp.y, &l[2], 4);
                            *(uint2*)(Chi + (long long)m * ldc + n) = hp;
                            *(uint2*)(Clo + (long long)m * ldc + n) = lp;
                        } else {
                            float4 o; o.x = v[0]; o.y = v[1]; o.z = v[2]; o.w = v[3];
                            *(float4*)(Cf + (long long)m * ldc + n) = o;
                        }
                    }
                }
            }
        }
    }
    TCGEN05_FENCE_BEFORE();
    __syncthreads();
    if (tid == 0) mbarrier_inval(sb + OFF_MBAR);
    if (wid == 0) TCGEN05_DEALLOC(tmem, 128);

#else  // ===== SIMT fallback (plain sm_103 pass; never runs on GB300) =====
    constexpr int FB_BK = 16;
    constexpr int FB_SROW = 132;
    float (*As)[FB_SROW] = (float(*)[FB_SROW])(smem);
    float (*Bs)[FB_SROW] = (float(*)[FB_SROW])(smem + FB_BK * FB_SROW * 4);

    const int tx = tid & 15;
    const int ty = tid >> 4;
    float acc[8][8] = {};

    for (int kt = 0; kt < K; kt += FB_BK) {
        {
            int m = m0 + (tid >> 1); m = min(m, M - 1);
            const int kk = (tid & 1) * 8;
            const __nv_bfloat16* ph = Ahi + (long long)m * K + kt + kk;
            const __nv_bfloat16* pl = Alo + (long long)m * K + kt + kk;
            #pragma unroll
            for (int e = 0; e < 8; e++)
                As[kk + e][tid >> 1] = __bfloat162float(ph[e]) + __bfloat162float(pl[e]);
            int n = n0 + (tid >> 1); n = min(n, Nn - 1);
            const __nv_bfloat16* qh = Bhi + (long long)n * K + kt + kk;
            const __nv_bfloat16* ql = Blo + (long long)n * K + kt + kk;
            #pragma unroll
            for (int e = 0; e < 8; e++)
                Bs[kk + e][tid >> 1] = __bfloat162float(qh[e]) + __bfloat162float(ql[e]);
        }
        __syncthreads();
        #pragma unroll
        for (int k = 0; k < FB_BK; k++) {
            float a[8], b[8];
            #pragma unroll
            for (int e = 0; e < 8; e++) { a[e] = As[k][ty * 8 + e]; b[e] = Bs[k][tx * 8 + e]; }
            #pragma unroll
            for (int i = 0; i < 8; i++)
                #pragma unroll
                for (int j = 0; j < 8; j++)
                    acc[i][j] += a[i] * b[j];
        }
        __syncthreads();
    }
    #pragma unroll
    for (int i = 0; i < 8; i++) {
        const int m = m0 + ty * 8 + i;
        if (m >= M) continue;
        #pragma unroll
        for (int j = 0; j < 8; j++) {
            const int n = n0 + tx * 8 + j;
            if (n >= Nn) continue;
            float v = acc[i][j];
            if (BIAS_MODE == 1) v += bias[m];
            if (BIAS_MODE == 2) v += bias[n];
            if (OUT_BF16) {
                split_store(v, Chi + (long long)m * ldc + n, Clo + (long long)m * ldc + n);
            } else {
                Cf[(long long)m * ldc + n] = v;
            }
        }
    }
#endif
}

// ===================== transpose + split x: [n][c][hw] -> [n][hw][c] =====================
__global__ __launch_bounds__(256)
void transpose_split_x(const float* __restrict__ bf,
                       __nv_bfloat16* __restrict__ xhi,
                       __nv_bfloat16* __restrict__ xlo)
{
    __shared__ float t[32][33];
    const int n = blockIdx.z;
    const int hw0 = blockIdx.x * 32;
    const int c0 = blockIdx.y * 32;
    const int tx = threadIdx.x & 31, ty = threadIdx.x >> 5;
    const float* src = bf + (size_t)n * C_DIM * HW_DIM;
    #pragma unroll
    for (int i = 0; i < 4; i++)
        t[ty + i * 8][tx] = src[(size_t)(c0 + ty + i * 8) * HW_DIM + hw0 + tx];
    __syncthreads();
    __nv_bfloat16* dh = xhi + (size_t)n * HW_DIM * C_DIM;
    __nv_bfloat16* dl = xlo + (size_t)n * HW_DIM * C_DIM;
    #pragma unroll
    for (int i = 0; i < 4; i++) {
        const int hw = hw0 + ty + i * 8;
        const float v = t[tx][ty + i * 8];
        __nv_bfloat16 h = __float2bfloat16(v);
        const size_t o = (size_t)hw * C_DIM + c0 + tx;
        dh[o] = h;
        dl[o] = __float2bfloat16(v - __bfloat162float(h));
    }
}

// ===================== split W (elementwise) =====================
__global__ __launch_bounds__(256)
void split_w(const float* __restrict__ W,
             __nv_bfloat16* __restrict__ whi, __nv_bfloat16* __restrict__ wlo)
{
    const int i = blockIdx.x * 256 + threadIdx.x;
    if (i < D_DIM * C_DIM) {
        const float v = W[i];
        __nv_bfloat16 h = __float2bfloat16(v);
        whi[i] = h;
        wlo[i] = __float2bfloat16(v - __bfloat162float(h));
    }
}

// ===================== softmax rows of 512 -> bf16 hi/lo planes =====================
__global__ __launch_bounds__(256)
void softmax_split(const float* __restrict__ S,
                   __nv_bfloat16* __restrict__ ahi, __nv_bfloat16* __restrict__ alo)
{
    const long long row = blockIdx.x;
    const float* p = S + row * D_DIM;
    const int t = threadIdx.x;

    const float a = p[t];
    const float b = p[t + 256];

    __shared__ float red_max[8];
    __shared__ float red_sum[8];

    float m = fmaxf(a, b);
    #pragma unroll
    for (int o = 16; o > 0; o >>= 1)
        m = fmaxf(m, __shfl_xor_sync(0xffffffffu, m, o));
    if ((t & 31) == 0) red_max[t >> 5] = m;
    __syncthreads();
    float rowmax = red_max[0];
    #pragma unroll
    for (int i = 1; i < 8; i++) rowmax = fmaxf(rowmax, red_max[i]);

    const float ea = __expf(a - rowmax);
    const float eb = __expf(b - rowmax);
    float s = ea + eb;
    #pragma unroll
    for (int o = 16; o > 0; o >>= 1)
        s += __shfl_xor_sync(0xffffffffu, s, o);
    if ((t & 31) == 0) red_sum[t >> 5] = s;
    __syncthreads();
    float tot = 0.f;
    #pragma unroll
    for (int i = 0; i < 8; i++) tot += red_sum[i];
    const float inv = 1.0f / tot;

    const float pa = ea * inv, pb = eb * inv;
    split_store(pa, (__nv_bfloat16*)ahi + row * D_DIM + t,
                    (__nv_bfloat16*)alo + row * D_DIM + t);
    split_store(pb, (__nv_bfloat16*)ahi + row * D_DIM + t + 256,
                    (__nv_bfloat16*)alo + row * D_DIM + t + 256);
}

extern "C" void kernel_launch(void* const* d_in, const int* in_sizes, int n_in,
                              void* d_out, int out_size)
{
    (void)in_sizes; (void)n_in; (void)out_size;
    const float* bf = (const float*)d_in[0];  // [N, C, HW]
    const float* Wq = (const float*)d_in[1];  // [D, C]
    const float* bq = (const float*)d_in[2];  // [D]
    const float* Wk = (const float*)d_in[3];
    const float* bk = (const float*)d_in[4];
    const float* Wv = (const float*)d_in[5];
    const float* bv = (const float*)d_in[6];
    float* out = (float*)d_out;               // [N, D, HW]

    __nv_bfloat16 *xh, *xl, *wh, *wl, *qh, *ql, *kh, *kl, *vh, *vl, *ah, *al;
    float *Sp;
    cudaGetSymbolAddress((void**)&xh, g_xt_hi);
    cudaGetSymbolAddress((void**)&xl, g_xt_lo);
    cudaGetSymbolAddress((void**)&wh, g_w_hi);
    cudaGetSymbolAddress((void**)&wl, g_w_lo);
    cudaGetSymbolAddress((void**)&qh, g_q_hi);
    cudaGetSymbolAddress((void**)&ql, g_q_lo);
    cudaGetSymbolAddress((void**)&kh, g_k_hi);
    cudaGetSymbolAddress((void**)&kl, g_k_lo);
    cudaGetSymbolAddress((void**)&vh, g_v_hi);
    cudaGetSymbolAddress((void**)&vl, g_v_lo);
    cudaGetSymbolAddress((void**)&ah, g_att_hi);
    cudaGetSymbolAddress((void**)&al, g_att_lo);
    cudaGetSymbolAddress((void**)&Sp, g_S);

    cudaFuncSetAttribute(tc_gemm_planes<1, true>,
        cudaFuncAttributeMaxDynamicSharedMemorySize, SMEM_BYTES);
    cudaFuncSetAttribute(tc_gemm_planes<2, true>,
        cudaFuncAttributeMaxDynamicSharedMemorySize, SMEM_BYTES);
    cudaFuncSetAttribute(tc_gemm_planes<0, false>,
        cudaFuncAttributeMaxDynamicSharedMemorySize, SMEM_BYTES);

    const dim3 blk(256);
    const size_t WSZ = (size_t)D_DIM * C_DIM;
    const long long sX  = (long long)HW_DIM * C_DIM;   // xt per-batch
    const long long sQ  = (long long)D_DIM * HW_DIM;   // q/k per-batch ([d][s])
    const long long sV  = (long long)HW_DIM * D_DIM;   // v per-batch ([s][d])
    const long long sS  = (long long)D_DIM * D_DIM;

    // 0) splits/transposes
    transpose_split_x<<<dim3(HW_DIM / 32, C_DIM / 32, N_B), blk>>>(bf, xh, xl);
    split_w<<<(D_DIM * C_DIM + 255) / 256, blk>>>(Wq, wh + 0 * WSZ, wl + 0 * WSZ);
    split_w<<<(D_DIM * C_DIM + 255) / 256, blk>>>(Wk, wh + 1 * WSZ, wl + 1 * WSZ);
    split_w<<<(D_DIM * C_DIM + 255) / 256, blk>>>(Wv, wh + 2 * WSZ, wl + 2 * WSZ);

    // 1) Q/K proj: M=d(512), N=s(3136), K=c(512). A=W planes, B=xT planes.
    //    Out planes [d][s] bf16 (+bias per-m).
    const dim3 g_qk((HW_DIM + 127) / 128, D_DIM / 128, N_B);      // (25, 4, 16)
    tc_gemm_planes<1, true><<<g_qk, blk, SMEM_BYTES>>>(
        wh + 0 * WSZ, wl + 0 * WSZ, xh, xl, bq, nullptr, qh, ql,
        D_DIM, HW_DIM, C_DIM, HW_DIM, 0, sX, sQ);
    tc_gemm_planes<1, true><<<g_qk, blk, SMEM_BYTES>>>(
        wh + 1 * WSZ, wl + 1 * WSZ, xh, xl, bk, nullptr, kh, kl,
        D_DIM, HW_DIM, C_DIM, HW_DIM, 0, sX, sQ);

    // 1b) V proj: M=s(3136), N=d(512), K=c(512). A=xT, B=Wv. Out [s][d] (+bias per-n).
    const dim3 g_v(D_DIM / 128, (HW_DIM + 127) / 128, N_B);       // (4, 25, 16)
    tc_gemm_planes<2, true><<<g_v, blk, SMEM_BYTES>>>(
        xh, xl, wh + 2 * WSZ, wl + 2 * WSZ, bv, nullptr, vh, vl,
        HW_DIM, D_DIM, C_DIM, D_DIM, sX, 0, sV);

    // 2) scores: M=d, N=e, K=s(3136). A=Q planes, B=K planes. Out fp32 S.
    const dim3 g_sc(D_DIM / 128, D_DIM / 128, N_B);               // (4, 4, 16)
    tc_gemm_planes<0, false><<<g_sc, blk, SMEM_BYTES>>>(
        qh, ql, kh, kl, nullptr, Sp, nullptr, nullptr,
        D_DIM, D_DIM, HW_DIM, D_DIM, sQ, sQ, sS);

    // 3) softmax -> att planes
    softmax_split<<<N_B * D_DIM, blk>>>(Sp, ah, al);

    // 4) out: M=d, N=s(3136), K=e(512). A=att planes, B=V planes. Out fp32.
    const dim3 g_out((HW_DIM + 127) / 128, D_DIM / 128, N_B);     // (25, 4, 16)
    tc_gemm_planes<0, false><<<g_out, blk, SMEM_BYTES>>>(
        ah, al, vh, vl, nullptr, out, nullptr, nullptr,
        D_DIM, HW_DIM, D_DIM, HW_DIM, sS, sV, (long long)D_DIM * HW_DIM);
}